// round 1
// baseline (speedup 1.0000x reference)
#include <cuda_runtime.h>

#define BB 2
#define TT 2048
#define DD 1024
#define HH 16
#define HD 64
#define MM (BB*TT)          // 4096
#define SCALING 0.125f      // 64^-0.5

// Scratch (allocation-free rule: __device__ globals)
__device__ float g_q[(size_t)BB*HH*TT*HD];   // [b,h,t,d]
__device__ float g_k[(size_t)BB*HH*TT*HD];
__device__ float g_v[(size_t)BB*HH*TT*HD];
__device__ float g_ao[(size_t)BB*TT*DD];     // attention output, [b,t,D]

// ---------------------------------------------------------------------------
// QKV projection: C[m,n] = sum_k X[m,k] * W[n,k] + bias[n]  (then *scale for Q)
// Tile 64x64, BK=16, 256 threads, 4x4 per thread. Output written in head layout.
// blockIdx.z selects Q/K/V.
// ---------------------------------------------------------------------------
__global__ __launch_bounds__(256) void gemm_qkv(
    const float* __restrict__ X,
    const float* __restrict__ Wq, const float* __restrict__ bq,
    const float* __restrict__ Wk, const float* __restrict__ bk,
    const float* __restrict__ Wv, const float* __restrict__ bv)
{
    const float* W; const float* bias; float* out; float scale;
    if (blockIdx.z == 0)      { W = Wq; bias = bq; out = g_q; scale = SCALING; }
    else if (blockIdx.z == 1) { W = Wk; bias = bk; out = g_k; scale = 1.0f; }
    else                      { W = Wv; bias = bv; out = g_v; scale = 1.0f; }

    __shared__ float As[16][64];   // [k][m] (transposed on store)
    __shared__ float Bs[16][64];   // [k][n]

    const int tid = threadIdx.x;
    const int tx = tid & 15, ty = tid >> 4;
    const int m0 = blockIdx.y * 64, n0 = blockIdx.x * 64;

    const int lr = tid >> 2;          // 0..63: tile row
    const int lc = (tid & 3) * 4;     // 0,4,8,12: k offset

    const float* Arow = X + (size_t)(m0 + lr) * DD;
    const float* Brow = W + (size_t)(n0 + lr) * DD;

    float c[4][4] = {};

    for (int k0 = 0; k0 < DD; k0 += 16) {
        float4 av = *(const float4*)(Arow + k0 + lc);
        float4 bv4 = *(const float4*)(Brow + k0 + lc);
        __syncthreads();
        As[lc+0][lr] = av.x;  As[lc+1][lr] = av.y;
        As[lc+2][lr] = av.z;  As[lc+3][lr] = av.w;
        Bs[lc+0][lr] = bv4.x; Bs[lc+1][lr] = bv4.y;
        Bs[lc+2][lr] = bv4.z; Bs[lc+3][lr] = bv4.w;
        __syncthreads();
        #pragma unroll
        for (int kk = 0; kk < 16; kk++) {
            float4 a = *(const float4*)&As[kk][ty*4];
            float4 b = *(const float4*)&Bs[kk][tx*4];
            float af[4] = {a.x, a.y, a.z, a.w};
            float bf[4] = {b.x, b.y, b.z, b.w};
            #pragma unroll
            for (int i = 0; i < 4; i++)
                #pragma unroll
                for (int j = 0; j < 4; j++)
                    c[i][j] += af[i] * bf[j];
        }
    }

    // Epilogue: (c + bias) * scale, written in [b,h,t,d] layout.
    const int h = n0 >> 6;                 // n0 multiple of 64 -> whole tile one head
    #pragma unroll
    for (int i = 0; i < 4; i++) {
        int m = m0 + ty*4 + i;
        int b = m >> 11;                   // T = 2048
        int t = m & (TT - 1);
        float4 o;
        o.x = (c[i][0] + bias[n0 + tx*4 + 0]) * scale;
        o.y = (c[i][1] + bias[n0 + tx*4 + 1]) * scale;
        o.z = (c[i][2] + bias[n0 + tx*4 + 2]) * scale;
        o.w = (c[i][3] + bias[n0 + tx*4 + 3]) * scale;
        *(float4*)&out[(((size_t)(b*HH + h))*TT + t)*HD + tx*4] = o;
    }
}

// ---------------------------------------------------------------------------
// Output projection: out[m,n] = sum_k g_ao[m,k] * Wo[n,k] + bo[n]
// ---------------------------------------------------------------------------
__global__ __launch_bounds__(256) void gemm_out(
    const float* __restrict__ Wo, const float* __restrict__ bo,
    float* __restrict__ out)
{
    __shared__ float As[16][64];
    __shared__ float Bs[16][64];

    const int tid = threadIdx.x;
    const int tx = tid & 15, ty = tid >> 4;
    const int m0 = blockIdx.y * 64, n0 = blockIdx.x * 64;

    const int lr = tid >> 2;
    const int lc = (tid & 3) * 4;

    const float* Arow = g_ao + (size_t)(m0 + lr) * DD;
    const float* Brow = Wo + (size_t)(n0 + lr) * DD;

    float c[4][4] = {};

    for (int k0 = 0; k0 < DD; k0 += 16) {
        float4 av = *(const float4*)(Arow + k0 + lc);
        float4 bv4 = *(const float4*)(Brow + k0 + lc);
        __syncthreads();
        As[lc+0][lr] = av.x;  As[lc+1][lr] = av.y;
        As[lc+2][lr] = av.z;  As[lc+3][lr] = av.w;
        Bs[lc+0][lr] = bv4.x; Bs[lc+1][lr] = bv4.y;
        Bs[lc+2][lr] = bv4.z; Bs[lc+3][lr] = bv4.w;
        __syncthreads();
        #pragma unroll
        for (int kk = 0; kk < 16; kk++) {
            float4 a = *(const float4*)&As[kk][ty*4];
            float4 b = *(const float4*)&Bs[kk][tx*4];
            float af[4] = {a.x, a.y, a.z, a.w};
            float bf[4] = {b.x, b.y, b.z, b.w};
            #pragma unroll
            for (int i = 0; i < 4; i++)
                #pragma unroll
                for (int j = 0; j < 4; j++)
                    c[i][j] += af[i] * bf[j];
        }
    }

    #pragma unroll
    for (int i = 0; i < 4; i++) {
        int m = m0 + ty*4 + i;
        float4 o;
        o.x = c[i][0] + bo[n0 + tx*4 + 0];
        o.y = c[i][1] + bo[n0 + tx*4 + 1];
        o.z = c[i][2] + bo[n0 + tx*4 + 2];
        o.w = c[i][3] + bo[n0 + tx*4 + 3];
        *(float4*)&out[(size_t)m * DD + n0 + tx*4] = o;
    }
}

// ---------------------------------------------------------------------------
// Single-pass attention (no max-subtraction needed: scores are O(1)):
//   e = f * exp(q.k);  out = (sum_s e * v) / (sum_s e)
// Block: one (b,h) pair x 64 query rows. Stream s in 64-wide tiles.
// Dynamic smem: Qs[64][64] (t,d) | Kt[64][64] (d,s) | Vs[64][64] (s,d) | Es[64][64] (t,s)
// ---------------------------------------------------------------------------
__global__ __launch_bounds__(256) void attn_kernel(const float* __restrict__ f)
{
    extern __shared__ float sm[];
    float* Qs = sm;              // [t][d]
    float* Kt = sm + 4096;       // [d][s]  (transposed)
    float* Vs = sm + 8192;       // [s][d]
    float* Es = sm + 12288;      // [t][s]

    const int tid = threadIdx.x;
    const int tx = tid & 15, ty = tid >> 4;
    const int bh = blockIdx.y;
    const int b = bh >> 4, h = bh & 15;
    const int t0 = blockIdx.x * 64;

    const float* Q = g_q + (size_t)bh * TT * HD;
    const float* K = g_k + (size_t)bh * TT * HD;
    const float* V = g_v + (size_t)bh * TT * HD;

    // Load Q tile [64 x 64] (natural layout)
    {
        int r = tid >> 2;
        int cq = (tid & 3) * 4;
        #pragma unroll
        for (int u = 0; u < 4; u++) {
            int c = cq + u * 16;
            float4 v4 = *(const float4*)(Q + (size_t)(t0 + r)*HD + c);
            *(float4*)&Qs[r*64 + c] = v4;
        }
    }

    float acc[4][4] = {};
    float dpart[4] = {};

    for (int s0 = 0; s0 < TT; s0 += 64) {
        __syncthreads();   // previous iteration's reads of Kt/Vs/Es done
        {
            int r = tid >> 2;
            int cq = (tid & 3) * 4;
            #pragma unroll
            for (int u = 0; u < 4; u++) {
                int c = cq + u * 16;
                float4 kv = *(const float4*)(K + (size_t)(s0 + r)*HD + c);
                Kt[(c+0)*64 + r] = kv.x;
                Kt[(c+1)*64 + r] = kv.y;
                Kt[(c+2)*64 + r] = kv.z;
                Kt[(c+3)*64 + r] = kv.w;
                float4 vv = *(const float4*)(V + (size_t)(s0 + r)*HD + c);
                *(float4*)&Vs[r*64 + c] = vv;
            }
        }
        __syncthreads();

        // S = Q @ K^T  (this block's 64x64 tile), 4x4 per thread
        float sv[4][4] = {};
        #pragma unroll 16
        for (int d = 0; d < 64; d++) {
            float a0 = Qs[(ty*4+0)*64 + d];
            float a1 = Qs[(ty*4+1)*64 + d];
            float a2 = Qs[(ty*4+2)*64 + d];
            float a3 = Qs[(ty*4+3)*64 + d];
            float4 b4 = *(const float4*)&Kt[d*64 + tx*4];
            float bf[4] = {b4.x, b4.y, b4.z, b4.w};
            #pragma unroll
            for (int j = 0; j < 4; j++) {
                sv[0][j] += a0 * bf[j];
                sv[1][j] += a1 * bf[j];
                sv[2][j] += a2 * bf[j];
                sv[3][j] += a3 * bf[j];
            }
        }

        // e = f * exp(S); accumulate row denominators; stash e in smem
        #pragma unroll
        for (int i = 0; i < 4; i++) {
            int t = t0 + ty*4 + i;
            float4 f4 = *(const float4*)(f + ((size_t)b*TT + t)*TT + s0 + tx*4);
            float e0 = f4.x * __expf(sv[i][0]);
            float e1 = f4.y * __expf(sv[i][1]);
            float e2 = f4.z * __expf(sv[i][2]);
            float e3 = f4.w * __expf(sv[i][3]);
            dpart[i] += (e0 + e1) + (e2 + e3);
            *(float4*)&Es[(ty*4+i)*64 + tx*4] = make_float4(e0, e1, e2, e3);
        }
        __syncthreads();

        // acc += E @ V
        #pragma unroll 16
        for (int s = 0; s < 64; s++) {
            float e0 = Es[(ty*4+0)*64 + s];
            float e1 = Es[(ty*4+1)*64 + s];
            float e2 = Es[(ty*4+2)*64 + s];
            float e3 = Es[(ty*4+3)*64 + s];
            float4 v4 = *(const float4*)&Vs[s*64 + tx*4];
            float vf[4] = {v4.x, v4.y, v4.z, v4.w};
            #pragma unroll
            for (int j = 0; j < 4; j++) {
                acc[0][j] += e0 * vf[j];
                acc[1][j] += e1 * vf[j];
                acc[2][j] += e2 * vf[j];
                acc[3][j] += e3 * vf[j];
            }
        }
    }

    // Reduce denominators across tx (reuse Kt as scratch)
    __syncthreads();
    #pragma unroll
    for (int i = 0; i < 4; i++) Kt[(ty*4+i)*64 + tx] = dpart[i];
    __syncthreads();

    #pragma unroll
    for (int i = 0; i < 4; i++) {
        float s = 0.0f;
        #pragma unroll
        for (int x = 0; x < 16; x++) s += Kt[(ty*4+i)*64 + x];
        float inv = 1.0f / s;
        int t = t0 + ty*4 + i;
        float4 o = make_float4(acc[i][0]*inv, acc[i][1]*inv,
                               acc[i][2]*inv, acc[i][3]*inv);
        // write directly in [b, t, h*64+dh] layout for final projection
        *(float4*)&g_ao[((size_t)b*TT + t)*DD + h*HD + tx*4] = o;
    }
}

// ---------------------------------------------------------------------------
extern "C" void kernel_launch(void* const* d_in, const int* in_sizes, int n_in,
                              void* d_out, int out_size)
{
    const float* hs = (const float*)d_in[0];
    const float* f  = (const float*)d_in[1];
    const float* Wq = (const float*)d_in[2];
    const float* bq = (const float*)d_in[3];
    const float* Wk = (const float*)d_in[4];
    const float* bk = (const float*)d_in[5];
    const float* Wv = (const float*)d_in[6];
    const float* bv = (const float*)d_in[7];
    const float* Wo = (const float*)d_in[8];
    const float* bo = (const float*)d_in[9];
    float* out = (float*)d_out;

    // 64 KB dynamic smem for the attention kernel (above the 48 KB static cap).
    // cudaFuncSetAttribute does not enqueue stream work: graph-capture safe.
    cudaFuncSetAttribute(attn_kernel,
                         cudaFuncAttributeMaxDynamicSharedMemorySize, 65536);

    dim3 blk(256);
    gemm_qkv<<<dim3(DD/64, MM/64, 3), blk>>>(hs, Wq, bq, Wk, bk, Wv, bv);
    attn_kernel<<<dim3(TT/64, BB*HH), blk, 65536>>>(f);
    gemm_out<<<dim3(DD/64, MM/64), blk>>>(Wo, bo, out);
}

// round 7
// speedup vs baseline: 1.5661x; 1.5661x over previous
#include <cuda_runtime.h>
#include <cstdint>

#define BB 2
#define TT 2048
#define DD 1024
#define HH 16
#define HD 64
#define MM (BB*TT)          // 4096
#define SCALING 0.125f      // 64^-0.5

// Scratch (allocation-free rule: __device__ globals)
__device__ float g_q[(size_t)BB*HH*TT*HD];   // [b,h,t,d]
__device__ float g_k[(size_t)BB*HH*TT*HD];
__device__ float g_v[(size_t)BB*HH*TT*HD];
__device__ float g_ao[(size_t)BB*TT*DD];     // attention output, [b,t,D]

// ---------------------------------------------------------------------------
// tf32 helpers
// ---------------------------------------------------------------------------
__device__ __forceinline__ uint32_t f2tf32(float x) {
    uint32_t u;
    asm("cvt.rna.tf32.f32 %0, %1;" : "=r"(u) : "f"(x));
    return u;
}

__device__ __forceinline__ void mma16n8k8(float c[4],
                                          const uint32_t a[4],
                                          const uint32_t b[2]) {
    asm volatile(
        "mma.sync.aligned.m16n8k8.row.col.f32.tf32.tf32.f32 "
        "{%0,%1,%2,%3},{%4,%5,%6,%7},{%8,%9},{%0,%1,%2,%3};"
        : "+f"(c[0]), "+f"(c[1]), "+f"(c[2]), "+f"(c[3])
        : "r"(a[0]), "r"(a[1]), "r"(a[2]), "r"(a[3]),
          "r"(b[0]), "r"(b[1]));
}

// ---------------------------------------------------------------------------
// tf32 tensor-core GEMM body: C[m,n] = sum_k A[m,k]*B[n,k]   (C = A @ B^T)
// Block 128x128, K-chunk 16, 256 threads = 8 warps (4 m x 2 n),
// warp tile 32(m) x 64(n) = 2 x 8 mma tiles of m16n8k8.
// Smem [row][k] stride 20: fragment LDS conflict-free.
// Register-prefetch of next K-chunk overlaps LDG with mma.
// ---------------------------------------------------------------------------
#define SK 20

__device__ __forceinline__ void tgemm_body(
    const float* __restrict__ A, const float* __restrict__ B,
    int m0, int n0,
    uint32_t (*As)[SK], uint32_t (*Bs)[SK],
    float c[2][8][4])
{
    const int tid  = threadIdx.x;
    const int warp = tid >> 5, lane = tid & 31;
    const int g = lane >> 2, t4 = lane & 3;
    const int wm = warp >> 1, wn = warp & 1;       // 4 x 2 warp grid
    const int lr  = tid >> 1;                      // 0..127: tile row
    const int lk8 = (tid & 1) * 8;                 // k-offset 0 or 8

    const float* Arow = A + (size_t)(m0 + lr) * DD + lk8;
    const float* Brow = B + (size_t)(n0 + lr) * DD + lk8;

    // prefetch chunk 0
    float4 pa0 = *(const float4*)(Arow);
    float4 pa1 = *(const float4*)(Arow + 4);
    float4 pb0 = *(const float4*)(Brow);
    float4 pb1 = *(const float4*)(Brow + 4);

    for (int k0 = 0; k0 < DD; k0 += 16) {
        __syncthreads();   // previous chunk's mma reads done
        {
            uint32_t* ad = &As[lr][lk8];
            ad[0]=f2tf32(pa0.x); ad[1]=f2tf32(pa0.y);
            ad[2]=f2tf32(pa0.z); ad[3]=f2tf32(pa0.w);
            ad[4]=f2tf32(pa1.x); ad[5]=f2tf32(pa1.y);
            ad[6]=f2tf32(pa1.z); ad[7]=f2tf32(pa1.w);
            uint32_t* bd = &Bs[lr][lk8];
            bd[0]=f2tf32(pb0.x); bd[1]=f2tf32(pb0.y);
            bd[2]=f2tf32(pb0.z); bd[3]=f2tf32(pb0.w);
            bd[4]=f2tf32(pb1.x); bd[5]=f2tf32(pb1.y);
            bd[6]=f2tf32(pb1.z); bd[7]=f2tf32(pb1.w);
        }
        __syncthreads();

        const int nxt = k0 + 16;
        if (nxt < DD) {   // prefetch next chunk while mma runs
            pa0 = *(const float4*)(Arow + nxt);
            pa1 = *(const float4*)(Arow + nxt + 4);
            pb0 = *(const float4*)(Brow + nxt);
            pb1 = *(const float4*)(Brow + nxt + 4);
        }

        #pragma unroll
        for (int kk = 0; kk < 16; kk += 8) {
            uint32_t af[2][4];
            uint32_t bf[8][2];
            #pragma unroll
            for (int mt = 0; mt < 2; mt++) {
                int r = wm*32 + mt*16;
                af[mt][0] = As[r + g     ][kk + t4];
                af[mt][1] = As[r + g + 8 ][kk + t4];
                af[mt][2] = As[r + g     ][kk + t4 + 4];
                af[mt][3] = As[r + g + 8 ][kk + t4 + 4];
            }
            #pragma unroll
            for (int nt = 0; nt < 8; nt++) {
                int rn = wn*64 + nt*8;
                bf[nt][0] = Bs[rn + g][kk + t4];
                bf[nt][1] = Bs[rn + g][kk + t4 + 4];
            }
            #pragma unroll
            for (int mt = 0; mt < 2; mt++)
                #pragma unroll
                for (int nt = 0; nt < 8; nt++)
                    mma16n8k8(c[mt][nt], af[mt], bf[nt]);
        }
    }
}

// ---------------------------------------------------------------------------
// QKV projection (tensor core); blockIdx.z selects Q/K/V. Head-layout output.
// ---------------------------------------------------------------------------
__global__ __launch_bounds__(256, 2) void gemm_qkv(
    const float* __restrict__ X,
    const float* __restrict__ Wq, const float* __restrict__ bq,
    const float* __restrict__ Wk, const float* __restrict__ bk,
    const float* __restrict__ Wv, const float* __restrict__ bv)
{
    const float* W; const float* bias; float* out; float scale;
    if (blockIdx.z == 0)      { W = Wq; bias = bq; out = g_q; scale = SCALING; }
    else if (blockIdx.z == 1) { W = Wk; bias = bk; out = g_k; scale = 1.0f; }
    else                      { W = Wv; bias = bv; out = g_v; scale = 1.0f; }

    __shared__ uint32_t As[128][SK];
    __shared__ uint32_t Bs[128][SK];

    const int m0 = blockIdx.y * 128, n0 = blockIdx.x * 128;
    float c[2][8][4] = {};
    tgemm_body(X, W, m0, n0, As, Bs, c);

    const int tid  = threadIdx.x;
    const int warp = tid >> 5, lane = tid & 31;
    const int g = lane >> 2, t4 = lane & 3;
    const int wm = warp >> 1, wn = warp & 1;

    #pragma unroll
    for (int mt = 0; mt < 2; mt++) {
        #pragma unroll
        for (int nt = 0; nt < 8; nt++) {
            int n  = n0 + wn*64 + nt*8 + 2*t4;
            int h  = n >> 6, dh = n & 63;
            float bx = bias[n], by = bias[n+1];
            #pragma unroll
            for (int half = 0; half < 2; half++) {
                int m = m0 + wm*32 + mt*16 + g + half*8;
                int b = m >> 11;
                int tt = m & (TT - 1);
                float2 o;
                o.x = (c[mt][nt][half*2+0] + bx) * scale;
                o.y = (c[mt][nt][half*2+1] + by) * scale;
                *(float2*)&out[(((size_t)(b*HH + h))*TT + tt)*HD + dh] = o;
            }
        }
    }
}

// ---------------------------------------------------------------------------
// Output projection (tensor core): out = g_ao @ Wo^T + bo
// ---------------------------------------------------------------------------
__global__ __launch_bounds__(256, 2) void gemm_out(
    const float* __restrict__ Wo, const float* __restrict__ bo,
    float* __restrict__ out)
{
    __shared__ uint32_t As[128][SK];
    __shared__ uint32_t Bs[128][SK];

    const int m0 = blockIdx.y * 128, n0 = blockIdx.x * 128;
    float c[2][8][4] = {};
    tgemm_body(g_ao, Wo, m0, n0, As, Bs, c);

    const int tid  = threadIdx.x;
    const int warp = tid >> 5, lane = tid & 31;
    const int g = lane >> 2, t4 = lane & 3;
    const int wm = warp >> 1, wn = warp & 1;

    #pragma unroll
    for (int mt = 0; mt < 2; mt++) {
        #pragma unroll
        for (int nt = 0; nt < 8; nt++) {
            int n = n0 + wn*64 + nt*8 + 2*t4;
            float bx = bo[n], by = bo[n+1];
            #pragma unroll
            for (int half = 0; half < 2; half++) {
                int m = m0 + wm*32 + mt*16 + g + half*8;
                float2 o;
                o.x = c[mt][nt][half*2+0] + bx;
                o.y = c[mt][nt][half*2+1] + by;
                *(float2*)&out[(size_t)m * DD + n] = o;
            }
        }
    }
}

// ---------------------------------------------------------------------------
// Single-pass attention (unchanged R1, fp32 SIMT — verified math):
//   e = f*exp(q.k);  out = sum_s(e*v)/sum_s(e)
// Block: one (b,h) x 128 query rows. s streamed in 64-wide tiles.
// ---------------------------------------------------------------------------
#define KT_S 68
#define ES_S 68

__global__ __launch_bounds__(256, 2) void attn_kernel(const float* __restrict__ f)
{
    extern __shared__ float sm[];
    float* Qt = sm;                        // [d][t]  64 x 128
    float* Kt = Qt + 64*128;               // [d][s]  64 x 68
    float* Vs = Kt + 64*KT_S;              // [s][d]  64 x 64
    float* Es = Vs + 64*64;                // [t][s]  128 x 68

    const int tid = threadIdx.x;
    const int tx = tid & 15, ty = tid >> 4;
    const int bh = blockIdx.y;
    const int b = bh >> 4, h = bh & 15;
    const int t0 = blockIdx.x * 128;

    const float* Q = g_q + (size_t)bh * TT * HD;
    const float* K = g_k + (size_t)bh * TT * HD;
    const float* V = g_v + (size_t)bh * TT * HD;

    // Load Q tile [128 x 64] transposed -> Qt[d][t]
    {
        int r = tid >> 1;
        int c0 = (tid & 1) * 32;
        const float* Qrow = Q + (size_t)(t0 + r)*HD + c0;
        #pragma unroll
        for (int u = 0; u < 8; u++) {
            float4 q4 = *(const float4*)(Qrow + u*4);
            int c = c0 + u*4;
            Qt[(c+0)*128 + r] = q4.x;
            Qt[(c+1)*128 + r] = q4.y;
            Qt[(c+2)*128 + r] = q4.z;
            Qt[(c+3)*128 + r] = q4.w;
        }
    }

    float acc[8][4] = {};
    float dpart[8] = {};

    const int kr = tid >> 2;
    const int kc = (tid & 3) * 4;

    for (int s0 = 0; s0 < TT; s0 += 64) {
        __syncthreads();
        #pragma unroll
        for (int u = 0; u < 4; u++) {
            int c = kc + u*16;
            float4 kv = *(const float4*)(K + (size_t)(s0 + kr)*HD + c);
            Kt[(c+0)*KT_S + kr] = kv.x;
            Kt[(c+1)*KT_S + kr] = kv.y;
            Kt[(c+2)*KT_S + kr] = kv.z;
            Kt[(c+3)*KT_S + kr] = kv.w;
            *(float4*)&Vs[kr*64 + c] = *(const float4*)(V + (size_t)(s0 + kr)*HD + c);
        }
        __syncthreads();

        float sv[8][4] = {};
        #pragma unroll 8
        for (int d = 0; d < 64; d++) {
            float4 a0 = *(const float4*)&Qt[d*128 + ty*4];
            float4 a1 = *(const float4*)&Qt[d*128 + 64 + ty*4];
            float4 b4 = *(const float4*)&Kt[d*KT_S + tx*4];
            float av[8] = {a0.x,a0.y,a0.z,a0.w, a1.x,a1.y,a1.z,a1.w};
            float bv[4] = {b4.x,b4.y,b4.z,b4.w};
            #pragma unroll
            for (int i = 0; i < 8; i++)
                #pragma unroll
                for (int j = 0; j < 4; j++)
                    sv[i][j] += av[i] * bv[j];
        }

        #pragma unroll
        for (int i = 0; i < 8; i++) {
            int tl = (i < 4) ? (ty*4 + i) : (64 + ty*4 + i - 4);
            int t = t0 + tl;
            float4 f4 = *(const float4*)(f + ((size_t)b*TT + t)*TT + s0 + tx*4);
            float e0 = f4.x * __expf(sv[i][0]);
            float e1 = f4.y * __expf(sv[i][1]);
            float e2 = f4.z * __expf(sv[i][2]);
            float e3 = f4.w * __expf(sv[i][3]);
            dpart[i] += (e0 + e1) + (e2 + e3);
            *(float4*)&Es[tl*ES_S + tx*4] = make_float4(e0, e1, e2, e3);
        }
        __syncthreads();

        #pragma unroll 8
        for (int s = 0; s < 64; s++) {
            float4 v4 = *(const float4*)&Vs[s*64 + tx*4];
            float vf[4] = {v4.x, v4.y, v4.z, v4.w};
            #pragma unroll
            for (int i = 0; i < 8; i++) {
                int tl = (i < 4) ? (ty*4 + i) : (64 + ty*4 + i - 4);
                float e = Es[tl*ES_S + s];
                #pragma unroll
                for (int j = 0; j < 4; j++)
                    acc[i][j] += e * vf[j];
            }
        }
    }

    __syncthreads();
    float* red = Kt;
    #pragma unroll
    for (int i = 0; i < 8; i++) {
        int tl = (i < 4) ? (ty*4 + i) : (64 + ty*4 + i - 4);
        red[tl*17 + tx] = dpart[i];
    }
    __syncthreads();

    #pragma unroll
    for (int i = 0; i < 8; i++) {
        int tl = (i < 4) ? (ty*4 + i) : (64 + ty*4 + i - 4);
        float ssum = 0.0f;
        #pragma unroll
        for (int x = 0; x < 16; x++) ssum += red[tl*17 + x];
        float inv = 1.0f / ssum;
        int t = t0 + tl;
        float4 o = make_float4(acc[i][0]*inv, acc[i][1]*inv,
                               acc[i][2]*inv, acc[i][3]*inv);
        *(float4*)&g_ao[((size_t)b*TT + t)*DD + h*HD + tx*4] = o;
    }
}

// ---------------------------------------------------------------------------
extern "C" void kernel_launch(void* const* d_in, const int* in_sizes, int n_in,
                              void* d_out, int out_size)
{
    const float* hs = (const float*)d_in[0];
    const float* f  = (const float*)d_in[1];
    const float* Wq = (const float*)d_in[2];
    const float* bq = (const float*)d_in[3];
    const float* Wk = (const float*)d_in[4];
    const float* bk = (const float*)d_in[5];
    const float* Wv = (const float*)d_in[6];
    const float* bv = (const float*)d_in[7];
    const float* Wo = (const float*)d_in[8];
    const float* bo = (const float*)d_in[9];
    float* out = (float*)d_out;

    const int attn_smem = (64*128 + 64*KT_S + 64*64 + 128*ES_S) * 4;
    cudaFuncSetAttribute(attn_kernel,
                         cudaFuncAttributeMaxDynamicSharedMemorySize, attn_smem);

    dim3 blk(256);
    gemm_qkv<<<dim3(DD/128, MM/128, 3), blk>>>(hs, Wq, bq, Wk, bk, Wv, bv);
    attn_kernel<<<dim3(TT/128, BB*HH), blk, attn_smem>>>(f);
    gemm_out<<<dim3(DD/128, MM/128), blk>>>(Wo, bo, out);
}

// round 13
// speedup vs baseline: 2.3445x; 1.4971x over previous
#include <cuda_runtime.h>
#include <cstdint>

#define BB 2
#define TT 2048
#define DD 1024
#define HH 16
#define HD 64
#define MM (BB*TT)          // 4096
#define SCALING 0.125f      // 64^-0.5

// Scratch (allocation-free rule: __device__ globals)
__device__ float g_q[(size_t)BB*HH*TT*HD];   // [b,h,t,d]
__device__ float g_k[(size_t)BB*HH*TT*HD];
__device__ float g_v[(size_t)BB*HH*TT*HD];
__device__ float g_ao[(size_t)BB*TT*DD];     // attention output, [b,t,D]

// ---------------------------------------------------------------------------
// tf32 helpers
// ---------------------------------------------------------------------------
__device__ __forceinline__ uint32_t f2tf32(float x) {
    uint32_t u;
    asm("cvt.rna.tf32.f32 %0, %1;" : "=r"(u) : "f"(x));
    return u;
}

__device__ __forceinline__ void mma16n8k8(float c[4],
                                          const uint32_t a[4],
                                          const uint32_t b[2]) {
    asm volatile(
        "mma.sync.aligned.m16n8k8.row.col.f32.tf32.tf32.f32 "
        "{%0,%1,%2,%3},{%4,%5,%6,%7},{%8,%9},{%0,%1,%2,%3};"
        : "+f"(c[0]), "+f"(c[1]), "+f"(c[2]), "+f"(c[3])
        : "r"(a[0]), "r"(a[1]), "r"(a[2]), "r"(a[3]),
          "r"(b[0]), "r"(b[1]));
}

// ---------------------------------------------------------------------------
// tf32 tensor-core GEMM body: C[m,n] = sum_k A[m,k]*B[n,k]   (C = A @ B^T)
// Block 128x128, K-chunk 16, 256 threads = 8 warps (4 m x 2 n),
// warp tile 32(m) x 64(n). (Measured 87 TF/s — unchanged from R6.)
// ---------------------------------------------------------------------------
#define SK 20

__device__ __forceinline__ void tgemm_body(
    const float* __restrict__ A, const float* __restrict__ B,
    int m0, int n0,
    uint32_t (*As)[SK], uint32_t (*Bs)[SK],
    float c[2][8][4])
{
    const int tid  = threadIdx.x;
    const int warp = tid >> 5, lane = tid & 31;
    const int g = lane >> 2, t4 = lane & 3;
    const int wm = warp >> 1, wn = warp & 1;
    const int lr  = tid >> 1;
    const int lk8 = (tid & 1) * 8;

    const float* Arow = A + (size_t)(m0 + lr) * DD + lk8;
    const float* Brow = B + (size_t)(n0 + lr) * DD + lk8;

    float4 pa0 = *(const float4*)(Arow);
    float4 pa1 = *(const float4*)(Arow + 4);
    float4 pb0 = *(const float4*)(Brow);
    float4 pb1 = *(const float4*)(Brow + 4);

    for (int k0 = 0; k0 < DD; k0 += 16) {
        __syncthreads();
        {
            uint32_t* ad = &As[lr][lk8];
            ad[0]=f2tf32(pa0.x); ad[1]=f2tf32(pa0.y);
            ad[2]=f2tf32(pa0.z); ad[3]=f2tf32(pa0.w);
            ad[4]=f2tf32(pa1.x); ad[5]=f2tf32(pa1.y);
            ad[6]=f2tf32(pa1.z); ad[7]=f2tf32(pa1.w);
            uint32_t* bd = &Bs[lr][lk8];
            bd[0]=f2tf32(pb0.x); bd[1]=f2tf32(pb0.y);
            bd[2]=f2tf32(pb0.z); bd[3]=f2tf32(pb0.w);
            bd[4]=f2tf32(pb1.x); bd[5]=f2tf32(pb1.y);
            bd[6]=f2tf32(pb1.z); bd[7]=f2tf32(pb1.w);
        }
        __syncthreads();

        const int nxt = k0 + 16;
        if (nxt < DD) {
            pa0 = *(const float4*)(Arow + nxt);
            pa1 = *(const float4*)(Arow + nxt + 4);
            pb0 = *(const float4*)(Brow + nxt);
            pb1 = *(const float4*)(Brow + nxt + 4);
        }

        #pragma unroll
        for (int kk = 0; kk < 16; kk += 8) {
            uint32_t af[2][4];
            uint32_t bf[8][2];
            #pragma unroll
            for (int mt = 0; mt < 2; mt++) {
                int r = wm*32 + mt*16;
                af[mt][0] = As[r + g     ][kk + t4];
                af[mt][1] = As[r + g + 8 ][kk + t4];
                af[mt][2] = As[r + g     ][kk + t4 + 4];
                af[mt][3] = As[r + g + 8 ][kk + t4 + 4];
            }
            #pragma unroll
            for (int nt = 0; nt < 8; nt++) {
                int rn = wn*64 + nt*8;
                bf[nt][0] = Bs[rn + g][kk + t4];
                bf[nt][1] = Bs[rn + g][kk + t4 + 4];
            }
            #pragma unroll
            for (int mt = 0; mt < 2; mt++)
                #pragma unroll
                for (int nt = 0; nt < 8; nt++)
                    mma16n8k8(c[mt][nt], af[mt], bf[nt]);
        }
    }
}

// ---------------------------------------------------------------------------
// QKV projection (tensor core); blockIdx.z selects Q/K/V. Head-layout output.
// ---------------------------------------------------------------------------
__global__ __launch_bounds__(256, 2) void gemm_qkv(
    const float* __restrict__ X,
    const float* __restrict__ Wq, const float* __restrict__ bq,
    const float* __restrict__ Wk, const float* __restrict__ bk,
    const float* __restrict__ Wv, const float* __restrict__ bv)
{
    const float* W; const float* bias; float* out; float scale;
    if (blockIdx.z == 0)      { W = Wq; bias = bq; out = g_q; scale = SCALING; }
    else if (blockIdx.z == 1) { W = Wk; bias = bk; out = g_k; scale = 1.0f; }
    else                      { W = Wv; bias = bv; out = g_v; scale = 1.0f; }

    __shared__ uint32_t As[128][SK];
    __shared__ uint32_t Bs[128][SK];

    const int m0 = blockIdx.y * 128, n0 = blockIdx.x * 128;
    float c[2][8][4] = {};
    tgemm_body(X, W, m0, n0, As, Bs, c);

    const int tid  = threadIdx.x;
    const int warp = tid >> 5, lane = tid & 31;
    const int g = lane >> 2, t4 = lane & 3;
    const int wm = warp >> 1, wn = warp & 1;

    #pragma unroll
    for (int mt = 0; mt < 2; mt++) {
        #pragma unroll
        for (int nt = 0; nt < 8; nt++) {
            int n  = n0 + wn*64 + nt*8 + 2*t4;
            int h  = n >> 6, dh = n & 63;
            float bx = bias[n], by = bias[n+1];
            #pragma unroll
            for (int half = 0; half < 2; half++) {
                int m = m0 + wm*32 + mt*16 + g + half*8;
                int b = m >> 11;
                int tt = m & (TT - 1);
                float2 o;
                o.x = (c[mt][nt][half*2+0] + bx) * scale;
                o.y = (c[mt][nt][half*2+1] + by) * scale;
                *(float2*)&out[(((size_t)(b*HH + h))*TT + tt)*HD + dh] = o;
            }
        }
    }
}

// ---------------------------------------------------------------------------
// Output projection (tensor core): out = g_ao @ Wo^T + bo
// ---------------------------------------------------------------------------
__global__ __launch_bounds__(256, 2) void gemm_out(
    const float* __restrict__ Wo, const float* __restrict__ bo,
    float* __restrict__ out)
{
    __shared__ uint32_t As[128][SK];
    __shared__ uint32_t Bs[128][SK];

    const int m0 = blockIdx.y * 128, n0 = blockIdx.x * 128;
    float c[2][8][4] = {};
    tgemm_body(g_ao, Wo, m0, n0, As, Bs, c);

    const int tid  = threadIdx.x;
    const int warp = tid >> 5, lane = tid & 31;
    const int g = lane >> 2, t4 = lane & 3;
    const int wm = warp >> 1, wn = warp & 1;

    #pragma unroll
    for (int mt = 0; mt < 2; mt++) {
        #pragma unroll
        for (int nt = 0; nt < 8; nt++) {
            int n = n0 + wn*64 + nt*8 + 2*t4;
            float bx = bo[n], by = bo[n+1];
            #pragma unroll
            for (int half = 0; half < 2; half++) {
                int m = m0 + wm*32 + mt*16 + g + half*8;
                float2 o;
                o.x = c[mt][nt][half*2+0] + bx;
                o.y = c[mt][nt][half*2+1] + by;
                *(float2*)&out[(size_t)m * DD + n] = o;
            }
        }
    }
}

// ---------------------------------------------------------------------------
// Tensor-core single-pass attention: e = f*exp(q.k); out = sum(e*v)/sum(e)
// Block: one (b,h) x 128 t-rows; s streamed in 64-wide chunks.
// 8 warps as 4(m) x 2(n); warp tile 32(rows) x 32(cols).
// Q A-fragments preloaded in registers (loop-invariant).
// Smem: Ks[64][68] | Vs[64][72] | Es[128][68] (tf32) | red[128][2] (f32)
// ---------------------------------------------------------------------------
#define S_KS 68
#define S_VS 72
#define S_ES 68

__global__ __launch_bounds__(256) void attn_tc(const float* __restrict__ f)
{
    extern __shared__ uint32_t smu[];
    uint32_t* Ks = smu;                      // [64][S_KS]
    uint32_t* Vs = Ks + 64*S_KS;             // [64][S_VS]
    uint32_t* Es = Vs + 64*S_VS;             // [128][S_ES]
    float*   red = (float*)(Es + 128*S_ES);  // [128][2]

    const int tid  = threadIdx.x;
    const int warp = tid >> 5, lane = tid & 31;
    const int g = lane >> 2, t4 = lane & 3;
    const int wm = warp >> 1, wn = warp & 1;
    const int bh = blockIdx.y, b = bh >> 4, h = bh & 15;
    const int t0 = blockIdx.x * 128;

    const float* Q = g_q + (size_t)bh * TT * HD;
    const float* K = g_k + (size_t)bh * TT * HD;
    const float* V = g_v + (size_t)bh * TT * HD;

    // Preload Q A-fragments for the full k=64 (loop-invariant)
    uint32_t qa[2][8][4];
    #pragma unroll
    for (int mt = 0; mt < 2; mt++) {
        int r0 = t0 + wm*32 + mt*16;
        #pragma unroll
        for (int ks = 0; ks < 8; ks++) {
            qa[mt][ks][0] = f2tf32(Q[(size_t)(r0 + g    )*HD + ks*8 + t4    ]);
            qa[mt][ks][1] = f2tf32(Q[(size_t)(r0 + g + 8)*HD + ks*8 + t4    ]);
            qa[mt][ks][2] = f2tf32(Q[(size_t)(r0 + g    )*HD + ks*8 + t4 + 4]);
            qa[mt][ks][3] = f2tf32(Q[(size_t)(r0 + g + 8)*HD + ks*8 + t4 + 4]);
        }
    }

    float oacc[2][4][4] = {};
    float dpart[2][2] = {};

    const int lr = tid >> 2;            // 0..63 s-row for K/V staging
    const int lc = (tid & 3) * 16;      // col base

    for (int s0 = 0; s0 < TT; s0 += 64) {
        __syncthreads();    // prior EV reads of Vs/Es, QK reads of Ks done
        {
            const float* Kr = K + (size_t)(s0 + lr) * HD;
            const float* Vr = V + (size_t)(s0 + lr) * HD;
            #pragma unroll
            for (int u = 0; u < 4; u++) {
                int cc = lc + u*4;
                float4 kv = *(const float4*)(Kr + cc);
                uint4 kt; kt.x=f2tf32(kv.x); kt.y=f2tf32(kv.y);
                          kt.z=f2tf32(kv.z); kt.w=f2tf32(kv.w);
                *(uint4*)&Ks[lr*S_KS + cc] = kt;
                float4 vv = *(const float4*)(Vr + cc);
                uint4 vt; vt.x=f2tf32(vv.x); vt.y=f2tf32(vv.y);
                          vt.z=f2tf32(vv.z); vt.w=f2tf32(vv.w);
                *(uint4*)&Vs[lr*S_VS + cc] = vt;
            }
        }
        __syncthreads();

        // S = Q @ K^T : warp tile 32(t) x 32(s); B[k=d][n=s] = K[s][d]
        float c[2][4][4] = {};
        #pragma unroll
        for (int ks = 0; ks < 8; ks++) {
            uint32_t bf[4][2];
            #pragma unroll
            for (int nt = 0; nt < 4; nt++) {
                int sr = wn*32 + nt*8 + g;
                bf[nt][0] = Ks[sr*S_KS + ks*8 + t4    ];
                bf[nt][1] = Ks[sr*S_KS + ks*8 + t4 + 4];
            }
            #pragma unroll
            for (int mt = 0; mt < 2; mt++)
                #pragma unroll
                for (int nt = 0; nt < 4; nt++)
                    mma16n8k8(c[mt][nt], qa[mt][ks], bf[nt]);
        }

        // e = f * exp(S); accumulate denominators; store tf32 E to smem
        #pragma unroll
        for (int mt = 0; mt < 2; mt++) {
            #pragma unroll
            for (int nt = 0; nt < 4; nt++) {
                int row0 = t0 + wm*32 + mt*16 + g;
                int col  = s0 + wn*32 + nt*8 + 2*t4;
                const float* fb = f + ((size_t)b*TT + row0)*TT + col;
                float2 f0 = *(const float2*)fb;
                float2 f1 = *(const float2*)(fb + (size_t)8*TT);
                float e0 = f0.x * __expf(c[mt][nt][0]);
                float e1 = f0.y * __expf(c[mt][nt][1]);
                float e2 = f1.x * __expf(c[mt][nt][2]);
                float e3 = f1.y * __expf(c[mt][nt][3]);
                dpart[mt][0] += e0 + e1;
                dpart[mt][1] += e2 + e3;
                int er = wm*32 + mt*16 + g;
                int ec = wn*32 + nt*8 + 2*t4;
                uint2 p0; p0.x = f2tf32(e0); p0.y = f2tf32(e1);
                *(uint2*)&Es[er*S_ES + ec] = p0;
                uint2 p1; p1.x = f2tf32(e2); p1.y = f2tf32(e3);
                *(uint2*)&Es[(er+8)*S_ES + ec] = p1;
            }
        }
        __syncthreads();

        // acc += E @ V : warp tile 32(t) x 32(d); B[k=s][n=d] = V[s][d]
        #pragma unroll
        for (int ks = 0; ks < 8; ks++) {
            uint32_t af[2][4];
            uint32_t bf[4][2];
            #pragma unroll
            for (int mt = 0; mt < 2; mt++) {
                int er = wm*32 + mt*16;
                af[mt][0] = Es[(er + g    )*S_ES + ks*8 + t4    ];
                af[mt][1] = Es[(er + g + 8)*S_ES + ks*8 + t4    ];
                af[mt][2] = Es[(er + g    )*S_ES + ks*8 + t4 + 4];
                af[mt][3] = Es[(er + g + 8)*S_ES + ks*8 + t4 + 4];
            }
            #pragma unroll
            for (int nt = 0; nt < 4; nt++) {
                int dc = wn*32 + nt*8 + g;
                bf[nt][0] = Vs[(ks*8 + t4    )*S_VS + dc];
                bf[nt][1] = Vs[(ks*8 + t4 + 4)*S_VS + dc];
            }
            #pragma unroll
            for (int mt = 0; mt < 2; mt++)
                #pragma unroll
                for (int nt = 0; nt < 4; nt++)
                    mma16n8k8(oacc[mt][nt], af[mt], bf[nt]);
        }
    }

    // Row-denominator reduction: shfl over t4-group, then smem across wn
    #pragma unroll
    for (int mt = 0; mt < 2; mt++) {
        #pragma unroll
        for (int half = 0; half < 2; half++) {
            float v = dpart[mt][half];
            v += __shfl_xor_sync(0xffffffffu, v, 1);
            v += __shfl_xor_sync(0xffffffffu, v, 2);
            if (t4 == 0)
                red[(wm*32 + mt*16 + g + half*8)*2 + wn] = v;
        }
    }
    __syncthreads();

    // Scale and write output in [b, t, h*64+d] layout
    #pragma unroll
    for (int mt = 0; mt < 2; mt++) {
        int rl0 = wm*32 + mt*16 + g;
        float inv0 = 1.0f / (red[rl0*2] + red[rl0*2+1]);
        float inv8 = 1.0f / (red[(rl0+8)*2] + red[(rl0+8)*2+1]);
        #pragma unroll
        for (int nt = 0; nt < 4; nt++) {
            int d = wn*32 + nt*8 + 2*t4;
            float2 o0, o1;
            o0.x = oacc[mt][nt][0]*inv0; o0.y = oacc[mt][nt][1]*inv0;
            o1.x = oacc[mt][nt][2]*inv8; o1.y = oacc[mt][nt][3]*inv8;
            int t_0 = t0 + rl0;
            *(float2*)&g_ao[((size_t)b*TT + t_0)*DD + h*HD + d] = o0;
            *(float2*)&g_ao[((size_t)b*TT + t_0 + 8)*DD + h*HD + d] = o1;
        }
    }
}

// ---------------------------------------------------------------------------
extern "C" void kernel_launch(void* const* d_in, const int* in_sizes, int n_in,
                              void* d_out, int out_size)
{
    const float* hs = (const float*)d_in[0];
    const float* f  = (const float*)d_in[1];
    const float* Wq = (const float*)d_in[2];
    const float* bq = (const float*)d_in[3];
    const float* Wk = (const float*)d_in[4];
    const float* bk = (const float*)d_in[5];
    const float* Wv = (const float*)d_in[6];
    const float* bv = (const float*)d_in[7];
    const float* Wo = (const float*)d_in[8];
    const float* bo = (const float*)d_in[9];
    float* out = (float*)d_out;

    const int attn_smem = (64*S_KS + 64*S_VS + 128*S_ES) * 4 + 128*2*4;
    cudaFuncSetAttribute(attn_tc,
                         cudaFuncAttributeMaxDynamicSharedMemorySize, attn_smem);

    dim3 blk(256);
    gemm_qkv<<<dim3(DD/128, MM/128, 3), blk>>>(hs, Wq, bq, Wk, bk, Wv, bv);
    attn_tc<<<dim3(TT/128, BB*HH), blk, attn_smem>>>(f);
    gemm_out<<<dim3(DD/128, MM/128), blk>>>(Wo, bo, out);
}